// round 1
// baseline (speedup 1.0000x reference)
#include <cuda_runtime.h>
#include <math.h>

// Problem constants
#define Bn 8
#define Tn 256
#define Vn 32
#define Dn 256
#define KT 16      // k-slice per smem stage
#define LDA 132    // padded smem row length (floats)

// Global accumulators (scratch; allocation-free per harness rules)
__device__ float g_an[Bn * Tn];  // sum_{j!=i,v,k} exp(s)   per (i,q)
__device__ float g_ap[Bn * Tn];  // sum_{v,q} exp(s_diag)   per (i,k)

__global__ void zero_acc_kernel() {
    int idx = blockIdx.x * blockDim.x + threadIdx.x;
    if (idx < Bn * Tn) {
        g_an[idx] = 0.f;
        g_ap[idx] = 0.f;
    }
}

// One block computes a 128x128 tile of S = f[i,v] @ fa[j,v]^T (K = D = 256),
// applies exp, and accumulates row/col sums into the global accumulators.
// blockIdx.x: bit0 = q-tile, bit1 = k-tile;  blockIdx.y = v;  blockIdx.z = i*8+j.
__global__ void __launch_bounds__(256, 2) infonce_main_kernel(
    const float* __restrict__ f, const float* __restrict__ fa)
{
    const int qt = blockIdx.x & 1;
    const int kt = (blockIdx.x >> 1) & 1;
    const int v  = blockIdx.y;
    const int i  = blockIdx.z >> 3;
    const int j  = blockIdx.z & 7;

    __shared__ float As[KT][LDA];
    __shared__ float Bs[KT][LDA];
    __shared__ float sAp[128];

    const int tid = threadIdx.x;
    const int tx  = tid & 15;   // column group
    const int ty  = tid >> 4;   // row group

    if (tid < 128) sAp[tid] = 0.f;

    // feature index [b, t, v, d] = ((b*T + t)*V + v)*D + d ; q-row stride = V*D
    const size_t ROWS = (size_t)Vn * Dn;  // 8192 floats between consecutive t
    const float* Ab = f  + (size_t)i * Tn * ROWS + (size_t)v * Dn + (size_t)(qt * 128) * ROWS;
    const float* Bb = fa + (size_t)j * Tn * ROWS + (size_t)v * Dn + (size_t)(kt * 128) * ROWS;

    // Cooperative load mapping: 256 threads, each loads 2 float4 rows per operand
    const int lq   = tid >> 2;          // 0..63
    const int ldc  = (tid & 3) << 2;    // 0,4,8,12 (d offset within KT slice)

    float acc[8][8];
    #pragma unroll
    for (int r = 0; r < 8; r++)
        #pragma unroll
        for (int c = 0; c < 8; c++) acc[r][c] = 0.f;

    for (int kb = 0; kb < Dn; kb += KT) {
        float4 a0 = *(const float4*)(Ab + (size_t)lq        * ROWS + kb + ldc);
        float4 a1 = *(const float4*)(Ab + (size_t)(lq + 64) * ROWS + kb + ldc);
        float4 b0 = *(const float4*)(Bb + (size_t)lq        * ROWS + kb + ldc);
        float4 b1 = *(const float4*)(Bb + (size_t)(lq + 64) * ROWS + kb + ldc);

        if (kb) __syncthreads();

        As[ldc + 0][lq] = a0.x; As[ldc + 1][lq] = a0.y;
        As[ldc + 2][lq] = a0.z; As[ldc + 3][lq] = a0.w;
        As[ldc + 0][lq + 64] = a1.x; As[ldc + 1][lq + 64] = a1.y;
        As[ldc + 2][lq + 64] = a1.z; As[ldc + 3][lq + 64] = a1.w;
        Bs[ldc + 0][lq] = b0.x; Bs[ldc + 1][lq] = b0.y;
        Bs[ldc + 2][lq] = b0.z; Bs[ldc + 3][lq] = b0.w;
        Bs[ldc + 0][lq + 64] = b1.x; Bs[ldc + 1][lq + 64] = b1.y;
        Bs[ldc + 2][lq + 64] = b1.z; Bs[ldc + 3][lq + 64] = b1.w;

        __syncthreads();

        #pragma unroll
        for (int kk = 0; kk < KT; kk++) {
            float a[8], b[8];
            *(float4*)(a)     = *(const float4*)&As[kk][ty * 4];
            *(float4*)(a + 4) = *(const float4*)&As[kk][64 + ty * 4];
            *(float4*)(b)     = *(const float4*)&Bs[kk][tx * 4];
            *(float4*)(b + 4) = *(const float4*)&Bs[kk][64 + tx * 4];
            #pragma unroll
            for (int r = 0; r < 8; r++)
                #pragma unroll
                for (int c = 0; c < 8; c++)
                    acc[r][c] = fmaf(a[r], b[c], acc[r][c]);
        }
    }

    // exp + per-thread partial sums
    float rowsum[8], colsum[8];
    #pragma unroll
    for (int r = 0; r < 8; r++) rowsum[r] = 0.f;
    #pragma unroll
    for (int c = 0; c < 8; c++) colsum[c] = 0.f;

    #pragma unroll
    for (int r = 0; r < 8; r++)
        #pragma unroll
        for (int c = 0; c < 8; c++) {
            float e = __expf(acc[r][c]);
            rowsum[r] += e;
            colsum[c] += e;
        }

    // reduce rowsums across tx (= lane & 15): xor shuffles stay within the 16-lane half
    #pragma unroll
    for (int r = 0; r < 8; r++) {
        float s = rowsum[r];
        s += __shfl_xor_sync(0xffffffffu, s, 1);
        s += __shfl_xor_sync(0xffffffffu, s, 2);
        s += __shfl_xor_sync(0xffffffffu, s, 4);
        s += __shfl_xor_sync(0xffffffffu, s, 8);
        rowsum[r] = s;
    }

    if (i != j) {
        // negatives: row sums into g_an[i, q]
        if (tx == 0) {
            #pragma unroll
            for (int r = 0; r < 8; r++) {
                int qloc = (r < 4) ? (ty * 4 + r) : (64 + ty * 4 + r - 4);
                atomicAdd(&g_an[i * Tn + qt * 128 + qloc], rowsum[r]);
            }
        }
    } else {
        // positives: column sums into g_ap[i, k] via shared staging
        #pragma unroll
        for (int c = 0; c < 8; c++) {
            int kloc = (c < 4) ? (tx * 4 + c) : (64 + tx * 4 + c - 4);
            atomicAdd(&sAp[kloc], colsum[c]);
        }
        __syncthreads();
        if (tid < 128) atomicAdd(&g_ap[i * Tn + kt * 128 + tid], sAp[tid]);
    }
}

__global__ void loss_kernel(float* out) {
    __shared__ float red[256];
    int tid = threadIdx.x;
    float s = 0.f;
    for (int idx = tid; idx < Bn * Tn; idx += 256)
        s += logf(g_an[idx]) - logf(g_ap[idx]);
    red[tid] = s;
    __syncthreads();
    for (int m = 128; m > 0; m >>= 1) {
        if (tid < m) red[tid] += red[tid + m];
        __syncthreads();
    }
    if (tid == 0) out[0] = red[0] / (float)Tn;
}

extern "C" void kernel_launch(void* const* d_in, const int* in_sizes, int n_in,
                              void* d_out, int out_size) {
    const float* f  = (const float*)d_in[0];   // feature     [B,T,V,D]
    const float* fa = (const float*)d_in[1];   // feature_aug [B,T,V,D]

    zero_acc_kernel<<<(Bn * Tn + 255) / 256, 256>>>();

    dim3 grid(4, Vn, Bn * Bn);   // (q/k tiles, v, i*8+j)
    infonce_main_kernel<<<grid, 256>>>(f, fa);

    loss_kernel<<<1, 256>>>((float*)d_out);
}

// round 3
// speedup vs baseline: 5.7739x; 5.7739x over previous
#include <cuda_runtime.h>
#include <cuda_bf16.h>
#include <cstdint>
#include <math.h>

#define Bn 8
#define Tn 256
#define Vn 32
#define Dn 256

// ---------------- device scratch (allocation-free) ----------------
__device__ float g_an[Bn * Tn];   // sum_{j!=i,v,k} exp(s) per (i,q)
__device__ float g_ap[Bn * Tn];   // sum_{v,q} exp(s_diag) per (i,k)
__device__ __nv_bfloat16 g_fb [Bn * Tn * Vn * Dn];  // bf16 feature
__device__ __nv_bfloat16 g_fab[Bn * Tn * Vn * Dn];  // bf16 feature_aug

// ---------------- PTX helpers (baseline ISA only: sm_80+) ----------------
__device__ __forceinline__ uint32_t smem_to_u32(const void* p) {
    uint32_t a;
    asm("{ .reg .u64 t; cvta.to.shared.u64 t, %1; cvt.u32.u64 %0, t; }"
        : "=r"(a) : "l"(p));
    return a;
}

#define CP_ASYNC16(saddr, gptr) \
    asm volatile("cp.async.cg.shared.global [%0], [%1], 16;" \
        :: "r"(saddr), "l"(gptr))
#define CP_COMMIT() asm volatile("cp.async.commit_group;")
#define CP_WAIT(n)  asm volatile("cp.async.wait_group %0;" :: "n"(n))

#define LDMATRIX_X4(r, addr) \
    asm volatile("ldmatrix.sync.aligned.m8n8.x4.shared.b16 {%0,%1,%2,%3}, [%4];" \
        : "=r"((r)[0]), "=r"((r)[1]), "=r"((r)[2]), "=r"((r)[3]) : "r"(addr))

#define MMA_BF16(d, a, b0, b1) \
    asm volatile("mma.sync.aligned.m16n8k16.row.col.f32.bf16.bf16.f32 " \
        "{%0,%1,%2,%3}, {%4,%5,%6,%7}, {%8,%9}, {%0,%1,%2,%3};" \
        : "+f"((d)[0]), "+f"((d)[1]), "+f"((d)[2]), "+f"((d)[3]) \
        : "r"((a)[0]), "r"((a)[1]), "r"((a)[2]), "r"((a)[3]), "r"(b0), "r"(b1))

// ---------------- layout constants ----------------
#define A_BYTES 16384              // 128 rows x 128B (64 bf16) per k-slice
#define B_BYTES 32768              // 256 rows x 128B
#define STAGE   (A_BYTES + B_BYTES)
#define SMEM_DYN (2 * STAGE)       // 98304 B

// ---------------- kernels ----------------
__global__ void cvt_kernel(const float* __restrict__ f, const float* __restrict__ fa) {
    int idx = blockIdx.x * blockDim.x + threadIdx.x;
    const int N4 = Bn * Tn * Vn * Dn / 4;
    if (idx < N4) {
        float4 a = ((const float4*)f)[idx];
        float4 b = ((const float4*)fa)[idx];
        __nv_bfloat162* oa = (__nv_bfloat162*)g_fb;
        __nv_bfloat162* ob = (__nv_bfloat162*)g_fab;
        oa[idx * 2 + 0] = __floats2bfloat162_rn(a.x, a.y);
        oa[idx * 2 + 1] = __floats2bfloat162_rn(a.z, a.w);
        ob[idx * 2 + 0] = __floats2bfloat162_rn(b.x, b.y);
        ob[idx * 2 + 1] = __floats2bfloat162_rn(b.z, b.w);
    }
    if (idx < Bn * Tn) { g_an[idx] = 0.f; g_ap[idx] = 0.f; }
}

// One CTA: S[128,256] = A[128,256] @ B[256,256]^T for one (i,j,v,qtile).
// 16 warps, warp tile 32x64 via mma.sync m16n8k16 bf16.
__global__ void __launch_bounds__(512, 1) infonce_hmma_kernel() {
    extern __shared__ char smem[];
    __shared__ float s_row[128];
    __shared__ float s_col[256];

    const uint32_t smem_base = smem_to_u32(smem);
    const int tid  = threadIdx.x;
    const int wid  = tid >> 5;
    const int lane = tid & 31;
    const int warp_m = wid >> 2;   // 0..3  -> m offset *32
    const int warp_n = wid & 3;    // 0..3  -> n offset *64

    const int qt = blockIdx.x;              // 0..1
    const int v  = blockIdx.y;              // 0..31
    const int i  = blockIdx.z >> 3;
    const int j  = blockIdx.z & 7;
    const bool diag = (i == j);

    if (tid < 128) s_row[tid] = 0.f;
    if (tid < 256) s_col[tid] = 0.f;

    const size_t RS = (size_t)Vn * Dn;      // 8192 elems between consecutive t
    const __nv_bfloat16* Ag = g_fb  + ((size_t)(i * Tn + qt * 128) * Vn + v) * Dn;
    const __nv_bfloat16* Bg = g_fab + ((size_t)(j * Tn) * Vn + v) * Dn;

    // prefetch lambda: k-slice ks (64 cols) into buffer buf
    auto prefetch = [&](int ks, int buf) {
        const uint32_t aBase = smem_base + buf * STAGE;
        const uint32_t bBase = aBase + A_BYTES;
        #pragma unroll
        for (int it = 0; it < 2; it++) {            // A: 1024 16B chunks
            int id = tid + it * 512;
            int row = id >> 3, c = id & 7;
            const __nv_bfloat16* g = Ag + (size_t)row * RS + ks * 64 + c * 8;
            uint32_t sa = aBase + row * 128 + ((c * 16) ^ ((row & 7) << 4));
            CP_ASYNC16(sa, g);
        }
        #pragma unroll
        for (int it = 0; it < 4; it++) {            // B: 2048 16B chunks
            int id = tid + it * 512;
            int row = id >> 3, c = id & 7;
            const __nv_bfloat16* g = Bg + (size_t)row * RS + ks * 64 + c * 8;
            uint32_t sb = bBase + row * 128 + ((c * 16) ^ ((row & 7) << 4));
            CP_ASYNC16(sb, g);
        }
        CP_COMMIT();
    };

    float acc[2][8][4];
    #pragma unroll
    for (int tm = 0; tm < 2; tm++)
        #pragma unroll
        for (int g = 0; g < 8; g++)
            #pragma unroll
            for (int c = 0; c < 4; c++) acc[tm][g][c] = 0.f;

    prefetch(0, 0);

    #pragma unroll
    for (int ks = 0; ks < 4; ks++) {
        const int buf = ks & 1;
        if (ks < 3) { prefetch(ks + 1, buf ^ 1); CP_WAIT(1); }
        else        { CP_WAIT(0); }
        __syncthreads();

        const uint32_t aBase = smem_base + buf * STAGE;
        const uint32_t bBase = aBase + A_BYTES;

        #pragma unroll
        for (int kk = 0; kk < 4; kk++) {
            uint32_t afr[2][4], bfr[4][4];
            #pragma unroll
            for (int tm = 0; tm < 2; tm++) {
                int r  = warp_m * 32 + tm * 16 + (lane & 7) + ((lane >> 3) & 1) * 8;
                int kb = kk * 32 + ((lane >> 4) & 1) * 16;
                LDMATRIX_X4(afr[tm], aBase + r * 128 + (kb ^ ((r & 7) << 4)));
            }
            #pragma unroll
            for (int g = 0; g < 4; g++) {
                int n  = warp_n * 64 + g * 16 + (lane & 7) + ((lane >> 4) & 1) * 8;
                int kb = kk * 32 + ((lane >> 3) & 1) * 16;
                LDMATRIX_X4(bfr[g], bBase + n * 128 + (kb ^ ((n & 7) << 4)));
            }
            #pragma unroll
            for (int tm = 0; tm < 2; tm++)
                #pragma unroll
                for (int g = 0; g < 4; g++) {
                    MMA_BF16(acc[tm][g * 2],     afr[tm], bfr[g][0], bfr[g][1]);
                    MMA_BF16(acc[tm][g * 2 + 1], afr[tm], bfr[g][2], bfr[g][3]);
                }
        }
        __syncthreads();
    }

    // ---- epilogue: exp + reductions ----
    // acc[tm][g][c]: rows r0 = warp_m*32+tm*16+lane/4 (c=0,1), r1 = r0+8 (c=2,3)
    //               cols c0 = warp_n*64+g*8+(lane&3)*2 (c=0,2), c1 = c0+1 (c=1,3)
    float e[2][8][4];
    #pragma unroll
    for (int tm = 0; tm < 2; tm++)
        #pragma unroll
        for (int g = 0; g < 8; g++)
            #pragma unroll
            for (int c = 0; c < 4; c++)
                e[tm][g][c] = __expf(acc[tm][g][c]);

    // row sums (over this warp's 64 n-cols)
    #pragma unroll
    for (int tm = 0; tm < 2; tm++) {
        float rs0 = 0.f, rs1 = 0.f;
        #pragma unroll
        for (int g = 0; g < 8; g++) {
            rs0 += e[tm][g][0] + e[tm][g][1];
            rs1 += e[tm][g][2] + e[tm][g][3];
        }
        rs0 += __shfl_xor_sync(0xffffffffu, rs0, 1);
        rs0 += __shfl_xor_sync(0xffffffffu, rs0, 2);
        rs1 += __shfl_xor_sync(0xffffffffu, rs1, 1);
        rs1 += __shfl_xor_sync(0xffffffffu, rs1, 2);
        if ((lane & 3) == 0) {
            int r = warp_m * 32 + tm * 16 + (lane >> 2);
            atomicAdd(&s_row[r], rs0);
            atomicAdd(&s_row[r + 8], rs1);
        }
    }

    if (diag) {
        // col sums (over this warp's 32 m-rows)
        #pragma unroll
        for (int g = 0; g < 8; g++) {
            float cs0 = e[0][g][0] + e[0][g][2] + e[1][g][0] + e[1][g][2];
            float cs1 = e[0][g][1] + e[0][g][3] + e[1][g][1] + e[1][g][3];
            cs0 += __shfl_xor_sync(0xffffffffu, cs0, 4);
            cs0 += __shfl_xor_sync(0xffffffffu, cs0, 8);
            cs0 += __shfl_xor_sync(0xffffffffu, cs0, 16);
            cs1 += __shfl_xor_sync(0xffffffffu, cs1, 4);
            cs1 += __shfl_xor_sync(0xffffffffu, cs1, 8);
            cs1 += __shfl_xor_sync(0xffffffffu, cs1, 16);
            if (lane < 4) {
                int c = warp_n * 64 + g * 8 + lane * 2;
                atomicAdd(&s_col[c], cs0);
                atomicAdd(&s_col[c + 1], cs1);
            }
        }
    }

    __syncthreads();

    if (!diag) {
        if (tid < 128) atomicAdd(&g_an[i * Tn + qt * 128 + tid], s_row[tid]);
    } else {
        if (tid < 256) atomicAdd(&g_ap[i * Tn + tid], s_col[tid]);
    }
}

__global__ void loss_kernel(float* out) {
    __shared__ float red[256];
    int tid = threadIdx.x;
    float s = 0.f;
    for (int idx = tid; idx < Bn * Tn; idx += 256)
        s += logf(g_an[idx]) - logf(g_ap[idx]);
    red[tid] = s;
    __syncthreads();
    for (int m = 128; m > 0; m >>= 1) {
        if (tid < m) red[tid] += red[tid + m];
        __syncthreads();
    }
    if (tid == 0) out[0] = red[0] / (float)Tn;
}

// ---------------- launch ----------------
extern "C" void kernel_launch(void* const* d_in, const int* in_sizes, int n_in,
                              void* d_out, int out_size) {
    const float* f  = (const float*)d_in[0];   // feature     [B,T,V,D]
    const float* fa = (const float*)d_in[1];   // feature_aug [B,T,V,D]

    cvt_kernel<<<(Bn * Tn * Vn * Dn / 4 + 255) / 256, 256>>>(f, fa);

    cudaFuncSetAttribute(infonce_hmma_kernel,
                         cudaFuncAttributeMaxDynamicSharedMemorySize, SMEM_DYN);
    dim3 grid(2, Vn, Bn * Bn);   // (qtile, v, i*8+j)
    infonce_hmma_kernel<<<grid, 512, SMEM_DYN>>>();

    loss_kernel<<<1, 256>>>((float*)d_out);
}

// round 4
// speedup vs baseline: 6.0376x; 1.0457x over previous
#include <cuda_runtime.h>
#include <cuda_bf16.h>
#include <cuda_fp8.h>
#include <cstdint>
#include <math.h>

#define Bn 8
#define Tn 256
#define Vn 32
#define Dn 256

// ---------------- device scratch (allocation-free) ----------------
__device__ float g_an[Bn * Tn];   // sum_{j!=i,v,k} exp(s) per (i,q)
__device__ float g_ap[Bn * Tn];   // sum_{v,q} exp(s_diag) per (i,k)
__device__ uint8_t g_fb8 [Bn * Tn * Vn * Dn];  // e4m3 feature      (x32 scaled)
__device__ uint8_t g_fab8[Bn * Tn * Vn * Dn];  // e4m3 feature_aug  (x32 scaled)

// ---------------- PTX helpers (baseline ISA, sm_89/90 features) ----------------
__device__ __forceinline__ uint32_t smem_to_u32(const void* p) {
    uint32_t a;
    asm("{ .reg .u64 t; cvta.to.shared.u64 t, %1; cvt.u32.u64 %0, t; }"
        : "=r"(a) : "l"(p));
    return a;
}

#define CP_ASYNC16(saddr, gptr) \
    asm volatile("cp.async.cg.shared.global [%0], [%1], 16;" \
        :: "r"(saddr), "l"(gptr))
#define CP_COMMIT() asm volatile("cp.async.commit_group;")
#define CP_WAIT0()  asm volatile("cp.async.wait_group 0;")

#define LDMATRIX_X4(r, addr) \
    asm volatile("ldmatrix.sync.aligned.m8n8.x4.shared.b16 {%0,%1,%2,%3}, [%4];" \
        : "=r"((r)[0]), "=r"((r)[1]), "=r"((r)[2]), "=r"((r)[3]) : "r"(addr))

// fp8 e4m3 MMA: D(4xf32) += A(4xb32: 16x32 e4m3) * B(2xb32: 32x8 e4m3)
#define MMA_FP8(d, a, b0, b1) \
    asm volatile("mma.sync.aligned.m16n8k32.row.col.f32.e4m3.e4m3.f32 " \
        "{%0,%1,%2,%3}, {%4,%5,%6,%7}, {%8,%9}, {%0,%1,%2,%3};" \
        : "+f"((d)[0]), "+f"((d)[1]), "+f"((d)[2]), "+f"((d)[3]) \
        : "r"((a)[0]), "r"((a)[1]), "r"((a)[2]), "r"((a)[3]), "r"(b0), "r"(b1))

// ---------------- layout ----------------
// fp8: full K=256 = 256B per row. A tile 128x256B = 32KB, B tile 128x256B = 32KB.
#define A_BYTES 32768
#define B_BYTES 32768
#define SMEM_DYN (A_BYTES + B_BYTES)   // 64 KB -> 2 CTAs/SM

// ---------------- kernels ----------------
__global__ void cvt_kernel(const float* __restrict__ f, const float* __restrict__ fa) {
    int idx = blockIdx.x * blockDim.x + threadIdx.x;
    const int N4 = Bn * Tn * Vn * Dn / 4;
    if (idx < N4) {
        float4 a = ((const float4*)f)[idx];
        float4 b = ((const float4*)fa)[idx];
        a.x *= 32.f; a.y *= 32.f; a.z *= 32.f; a.w *= 32.f;
        b.x *= 32.f; b.y *= 32.f; b.z *= 32.f; b.w *= 32.f;
        ((uint32_t*)g_fb8 )[idx] = __nv_fp8x4_e4m3(a).__x;
        ((uint32_t*)g_fab8)[idx] = __nv_fp8x4_e4m3(b).__x;
    }
    if (idx < Bn * Tn) { g_an[idx] = 0.f; g_ap[idx] = 0.f; }
}

// One CTA: S[128,128] = A[128,256] @ B[128,256]^T (fp8, scaled) for one
// (i,j,v,qt,kt); exp(S/1024) + row/col reductions. 8 warps, warp tile 32x64.
__global__ void __launch_bounds__(256, 2) infonce_fp8_kernel() {
    extern __shared__ char smem[];
    __shared__ float s_red[128];

    const uint32_t aBase = smem_to_u32(smem);
    const uint32_t bBase = aBase + A_BYTES;
    const int tid  = threadIdx.x;
    const int wid  = tid >> 5;
    const int lane = tid & 31;
    const int warp_m = wid >> 1;   // 0..3 -> m*32
    const int warp_n = wid & 1;    // 0..1 -> n*64

    const int qt = blockIdx.x & 1;
    const int kt = blockIdx.x >> 1;
    const int v  = blockIdx.y;
    const int i  = blockIdx.z >> 3;
    const int j  = blockIdx.z & 7;
    const bool diag = (i == j);

    if (tid < 128) s_red[tid] = 0.f;

    const size_t RS = (size_t)Vn * Dn;  // 8192 bytes between consecutive t
    const uint8_t* Ag = g_fb8  + ((size_t)(i * Tn + qt * 128) * Vn + v) * Dn;
    const uint8_t* Bg = g_fab8 + ((size_t)(j * Tn + kt * 128) * Vn + v) * Dn;

    // ---- load full tiles: 2048 16B chunks each, swizzled rows of 256B ----
    #pragma unroll
    for (int it = 0; it < 8; it++) {
        int id = tid + it * 256;
        int row = id >> 4, c = id & 15;
        uint32_t soff = (uint32_t)(row * 256) + (uint32_t)((c * 16) ^ ((row & 7) << 4));
        CP_ASYNC16(aBase + soff, Ag + (size_t)row * RS + c * 16);
    }
    #pragma unroll
    for (int it = 0; it < 8; it++) {
        int id = tid + it * 256;
        int row = id >> 4, c = id & 15;
        uint32_t soff = (uint32_t)(row * 256) + (uint32_t)((c * 16) ^ ((row & 7) << 4));
        CP_ASYNC16(bBase + soff, Bg + (size_t)row * RS + c * 16);
    }
    CP_COMMIT();

    float acc[2][8][4];
    #pragma unroll
    for (int tm = 0; tm < 2; tm++)
        #pragma unroll
        for (int g = 0; g < 8; g++)
            #pragma unroll
            for (int c = 0; c < 4; c++) acc[tm][g][c] = 0.f;

    CP_WAIT0();
    __syncthreads();

    // ---- 8 k-steps of 32 fp8 each ----
    #pragma unroll
    for (int kk = 0; kk < 8; kk++) {
        uint32_t afr[2][4];
        #pragma unroll
        for (int tm = 0; tm < 2; tm++) {
            int r = warp_m * 32 + tm * 16 + (lane & 7) + ((lane >> 3) & 1) * 8;
            uint32_t kb = (uint32_t)(kk * 32 + ((lane >> 4) & 1) * 16);
            LDMATRIX_X4(afr[tm], aBase + r * 256 + (kb ^ ((r & 7) << 4)));
        }
        #pragma unroll
        for (int gg = 0; gg < 4; gg++) {
            uint32_t bfr[4];
            int n = warp_n * 64 + gg * 16 + (lane & 7) + ((lane >> 4) & 1) * 8;
            uint32_t kb = (uint32_t)(kk * 32 + ((lane >> 3) & 1) * 16);
            LDMATRIX_X4(bfr, bBase + n * 256 + (kb ^ ((n & 7) << 4)));
            #pragma unroll
            for (int tm = 0; tm < 2; tm++) {
                MMA_FP8(acc[tm][gg * 2],     afr[tm], bfr[0], bfr[1]);
                MMA_FP8(acc[tm][gg * 2 + 1], afr[tm], bfr[2], bfr[3]);
            }
        }
    }

    // ---- epilogue: descale, exp, reductions ----
    // acc[tm][g][c]: row = warp_m*32 + tm*16 + lane/4 + (c>=2 ? 8:0)
    //               col = warp_n*64 + g*8 + (lane&3)*2 + (c&1)
    const float DS = 1.f / 1024.f;   // undo (32x)^2 input scaling

    if (!diag) {
        // negatives: row sums over this CTA's 128 k-cols
        #pragma unroll
        for (int tm = 0; tm < 2; tm++) {
            float rs0 = 0.f, rs1 = 0.f;
            #pragma unroll
            for (int g = 0; g < 8; g++) {
                rs0 += __expf(acc[tm][g][0] * DS) + __expf(acc[tm][g][1] * DS);
                rs1 += __expf(acc[tm][g][2] * DS) + __expf(acc[tm][g][3] * DS);
            }
            rs0 += __shfl_xor_sync(0xffffffffu, rs0, 1);
            rs0 += __shfl_xor_sync(0xffffffffu, rs0, 2);
            rs1 += __shfl_xor_sync(0xffffffffu, rs1, 1);
            rs1 += __shfl_xor_sync(0xffffffffu, rs1, 2);
            if ((lane & 3) == 0) {
                int r = warp_m * 32 + tm * 16 + (lane >> 2);
                atomicAdd(&s_red[r], rs0);
                atomicAdd(&s_red[r + 8], rs1);
            }
        }
        __syncthreads();
        if (tid < 128) atomicAdd(&g_an[i * Tn + qt * 128 + tid], s_red[tid]);
    } else {
        // positives: col sums over this CTA's 128 q-rows
        #pragma unroll
        for (int g = 0; g < 8; g++) {
            float cs0 = __expf(acc[0][g][0] * DS) + __expf(acc[0][g][2] * DS)
                      + __expf(acc[1][g][0] * DS) + __expf(acc[1][g][2] * DS);
            float cs1 = __expf(acc[0][g][1] * DS) + __expf(acc[0][g][3] * DS)
                      + __expf(acc[1][g][1] * DS) + __expf(acc[1][g][3] * DS);
            cs0 += __shfl_xor_sync(0xffffffffu, cs0, 4);
            cs0 += __shfl_xor_sync(0xffffffffu, cs0, 8);
            cs0 += __shfl_xor_sync(0xffffffffu, cs0, 16);
            cs1 += __shfl_xor_sync(0xffffffffu, cs1, 4);
            cs1 += __shfl_xor_sync(0xffffffffu, cs1, 8);
            cs1 += __shfl_xor_sync(0xffffffffu, cs1, 16);
            if (lane < 4) {
                int c = warp_n * 64 + g * 8 + lane * 2;
                atomicAdd(&s_red[c], cs0);
                atomicAdd(&s_red[c + 1], cs1);
            }
        }
        __syncthreads();
        if (tid < 128) atomicAdd(&g_ap[i * Tn + kt * 128 + tid], s_red[tid]);
    }
}

__global__ void loss_kernel(float* out) {
    __shared__ float red[256];
    int tid = threadIdx.x;
    float s = 0.f;
    for (int idx = tid; idx < Bn * Tn; idx += 256)
        s += logf(g_an[idx]) - logf(g_ap[idx]);
    red[tid] = s;
    __syncthreads();
    for (int m = 128; m > 0; m >>= 1) {
        if (tid < m) red[tid] += red[tid + m];
        __syncthreads();
    }
    if (tid == 0) out[0] = red[0] / (float)Tn;
}

// ---------------- launch ----------------
extern "C" void kernel_launch(void* const* d_in, const int* in_sizes, int n_in,
                              void* d_out, int out_size) {
    const float* f  = (const float*)d_in[0];   // feature     [B,T,V,D]
    const float* fa = (const float*)d_in[1];   // feature_aug [B,T,V,D]

    cvt_kernel<<<(Bn * Tn * Vn * Dn / 4 + 255) / 256, 256>>>(f, fa);

    cudaFuncSetAttribute(infonce_fp8_kernel,
                         cudaFuncAttributeMaxDynamicSharedMemorySize, SMEM_DYN);
    dim3 grid(4, Vn, Bn * Bn);   // (qt + 2*kt, v, i*8+j)
    infonce_fp8_kernel<<<grid, 256, SMEM_DYN>>>();

    loss_kernel<<<1, 256>>>((float*)d_out);
}